// round 9
// baseline (speedup 1.0000x reference)
#include <cuda_runtime.h>
#include <cuda_bf16.h>
#include <cstdint>
#include <cstddef>
#include <math.h>

#define N_NODES 50000
#define F_IN    128
#define F_HID   256
#define F_OUT   64
#define BUCKET  192
#define WCONV_THREADS (F_IN * F_HID + F_HID * F_OUT)
#define WCONV_BLOCKS  ((WCONV_THREADS + 255) / 256)

// ---------------- static scratch (no allocation allowed) ----------------
__device__ int   g_any_odd = 0;   // edge dtype probe: 1 => int32, 0 => int64
__device__ int   g_cnt [N_NODES];               // neighbor count (excl self)
__device__ __align__(16) float g_dinv[N_NODES];
__device__ int   g_bcol[(size_t)N_NODES * BUCKET];   // bucketed adjacency
__device__ __align__(16) __nv_bfloat16 g_w1t_hi[F_HID * F_IN];  // [256][128]
__device__ __align__(16) __nv_bfloat16 g_w1t_lo[F_HID * F_IN];
__device__ __align__(16) __nv_bfloat16 g_w2t_hi[F_OUT * F_HID]; // [64][256]
__device__ __align__(16) __nv_bfloat16 g_w2t_lo[F_OUT * F_HID];
__device__ __align__(16) float g_zs [(size_t)N_NODES * F_OUT];  // (h1@W2)*dinv

__device__ __forceinline__ int edge_at(const void* e, long long i, int is32) {
    if (is32) return ((const int*)e)[i];
    return (int)((const long long*)e)[i];
}

__device__ __forceinline__ void split_bf(float v, __nv_bfloat16& h, __nv_bfloat16& l) {
    h = __float2bfloat16(v);
    l = __float2bfloat16(v - __bfloat162float(h));
}
__device__ __forceinline__ uint32_t pack2(__nv_bfloat16 a, __nv_bfloat16 b) {
    return (uint32_t)__bfloat16_as_ushort(a) | ((uint32_t)__bfloat16_as_ushort(b) << 16);
}

#define MMA16816(d, a0,a1,a2,a3, b0,b1) \
  asm volatile("mma.sync.aligned.m16n8k16.row.col.f32.bf16.bf16.f32 " \
    "{%0,%1,%2,%3}, {%4,%5,%6,%7}, {%8,%9}, {%0,%1,%2,%3};" \
    : "+f"(d[0]), "+f"(d[1]), "+f"(d[2]), "+f"(d[3]) \
    : "r"(a0), "r"(a1), "r"(a2), "r"(a3), "r"(b0), "r"(b1))

// ---------------- pre: zero counts + dtype probe --------------
__global__ void k_pre(const int* __restrict__ ew, long long nwords) {
    long long i = (long long)blockIdx.x * blockDim.x + threadIdx.x;
    long long stride = (long long)gridDim.x * blockDim.x;
    for (long long q = i; q < N_NODES; q += stride)
        g_cnt[q] = 0;
    int any = 0;
    for (long long t = i * 2 + 1; t < nwords; t += 2 * stride)
        any |= ew[t];
    if (any) g_any_odd = 1;
}

// ------- bucket adjacency fill; spare blocks do weight split -----------
__global__ void k_fill_w(const void* __restrict__ edge, int E,
                         const float* __restrict__ W1, const float* __restrict__ W2,
                         int fillBlocks) {
    if (blockIdx.x < fillBlocks) {
        int is32 = g_any_odd;
        int i = blockIdx.x * blockDim.x + threadIdx.x;
        int stride = fillBlocks * blockDim.x;
        for (int e = i; e < E; e += stride) {
            int r = edge_at(edge, e, is32);
            int c = edge_at(edge, (long long)e + E, is32);
            int pos = atomicAdd(&g_cnt[r], 1);
            if (pos < BUCKET)
                g_bcol[(size_t)r * BUCKET + pos] = c;
        }
    } else {
        int i = (blockIdx.x - fillBlocks) * blockDim.x + threadIdx.x;
        if (i < F_IN * F_HID) {
            int k = i / F_HID, n = i % F_HID;
            __nv_bfloat16 h, l;
            split_bf(W1[i], h, l);
            g_w1t_hi[n * F_IN + k] = h;
            g_w1t_lo[n * F_IN + k] = l;
        }
        int j = i - F_IN * F_HID;
        if (j >= 0 && j < F_HID * F_OUT) {
            int k = j / F_OUT, n = j % F_OUT;
            __nv_bfloat16 h, l;
            split_bf(W2[j], h, l);
            g_w2t_hi[n * F_HID + k] = h;
            g_w2t_lo[n * F_HID + k] = l;
        }
    }
}

// ---------------- dinv = rsqrt(cnt + 1) ----------------
__global__ void k_dinv() {
    int i = blockIdx.x * blockDim.x + threadIdx.x;
    if (i < N_NODES)
        g_dinv[i] = rsqrtf((float)(g_cnt[i] + 1));
}

// ------ fused: gather agg1 tile -> smem, then zs = relu(A@W1+b1)@W2*dinv --
// smem (bf16 elems): A hi/lo 2*64*136, W1 hi/lo 2*64*136, H 2*64*72, W2 2*64*72
#define SM_A_HI 0
#define SM_A_LO 8704
#define SM_W_HI 17408
#define SM_W_LO 26112
#define SM_H_HI 34816
#define SM_H_LO 39424
#define SM_W2_HI 44032
#define SM_W2_LO 48640
#define SM_TOTAL_ELEMS 53248   // * 2 bytes = 106496

__global__ __launch_bounds__(256, 2) void k_mlp(const float* __restrict__ x,
                                                const float* __restrict__ b1) {
    extern __shared__ __nv_bfloat16 sm[];
    const int tid = threadIdx.x;
    const int lane = tid & 31, warp = tid >> 5;
    const int wm = warp & 3, wn = warp >> 2;
    const int g = lane >> 2, c = lane & 3;
    const int m_block = blockIdx.x * 64;

    // ---- gather phase: each warp aggregates 8 nodes into the A tile ----
    {
        size_t loff = (size_t)lane * 4;
#pragma unroll 1
        for (int j = 0; j < 8; j++) {
            int rl = warp * 8 + j;
            int node = m_block + rl;
            float4 acc = make_float4(0.f, 0.f, 0.f, 0.f);
            if (node < N_NODES) {
                float dvr = g_dinv[node];
                acc = *(const float4*)&x[(size_t)node * F_IN + loff];
                acc.x *= dvr; acc.y *= dvr; acc.z *= dvr; acc.w *= dvr;
                const int* bc = &g_bcol[(size_t)node * BUCKET];
                int cnt = g_cnt[node];
                if (cnt > BUCKET) cnt = BUCKET;
                int i = 0;
                for (; i + 4 <= cnt; i += 4) {
                    int c0 = bc[i];
                    int c1 = bc[i + 1];
                    int c2 = bc[i + 2];
                    int c3 = bc[i + 3];
                    float d0 = g_dinv[c0], d1 = g_dinv[c1];
                    float d2 = g_dinv[c2], d3 = g_dinv[c3];
                    float4 v0 = *(const float4*)&x[(size_t)c0 * F_IN + loff];
                    float4 v1 = *(const float4*)&x[(size_t)c1 * F_IN + loff];
                    float4 v2 = *(const float4*)&x[(size_t)c2 * F_IN + loff];
                    float4 v3 = *(const float4*)&x[(size_t)c3 * F_IN + loff];
                    acc.x += d0 * v0.x + d1 * v1.x + d2 * v2.x + d3 * v3.x;
                    acc.y += d0 * v0.y + d1 * v1.y + d2 * v2.y + d3 * v3.y;
                    acc.z += d0 * v0.z + d1 * v1.z + d2 * v2.z + d3 * v3.z;
                    acc.w += d0 * v0.w + d1 * v1.w + d2 * v2.w + d3 * v3.w;
                }
                for (; i < cnt; i++) {
                    int cc = bc[i];
                    float dc = g_dinv[cc];
                    float4 v = *(const float4*)&x[(size_t)cc * F_IN + loff];
                    acc.x += dc * v.x; acc.y += dc * v.y;
                    acc.z += dc * v.z; acc.w += dc * v.w;
                }
                acc.x *= dvr; acc.y *= dvr; acc.z *= dvr; acc.w *= dvr;
            }
            __nv_bfloat16 h0, l0, h1, l1, h2, l2, h3, l3;
            split_bf(acc.x, h0, l0); split_bf(acc.y, h1, l1);
            split_bf(acc.z, h2, l2); split_bf(acc.w, h3, l3);
            *(uint2*)&sm[SM_A_HI + rl * 136 + lane * 4] =
                make_uint2(pack2(h0, h1), pack2(h2, h3));
            *(uint2*)&sm[SM_A_LO + rl * 136 + lane * 4] =
                make_uint2(pack2(l0, l1), pack2(l2, l3));
        }
    }

    float acc2[4][4];
#pragma unroll
    for (int nt = 0; nt < 4; nt++)
#pragma unroll
        for (int q = 0; q < 4; q++) acc2[nt][q] = 0.f;

#pragma unroll
    for (int chunk = 0; chunk < 4; chunk++) {
        __syncthreads();   // A visible (iter 0); prior stage-B reads done (iter>0)
        {
            int row = tid >> 4;
            int col = (tid & 15) * 8;
#pragma unroll
            for (int r = 0; r < 4; r++) {
                int rr = row + r * 16;
                size_t go = (size_t)(chunk * 64 + rr) * F_IN + col;
                *(uint4*)&sm[SM_W_HI + rr * 136 + col] = *(const uint4*)(g_w1t_hi + go);
                *(uint4*)&sm[SM_W_LO + rr * 136 + col] = *(const uint4*)(g_w1t_lo + go);
            }
            int row2 = tid >> 3;
            int col2 = (tid & 7) * 8;
#pragma unroll
            for (int r = 0; r < 2; r++) {
                int rr = row2 + r * 32;
                size_t go = (size_t)rr * F_HID + chunk * 64 + col2;
                *(uint4*)&sm[SM_W2_HI + rr * 72 + col2] = *(const uint4*)(g_w2t_hi + go);
                *(uint4*)&sm[SM_W2_LO + rr * 72 + col2] = *(const uint4*)(g_w2t_lo + go);
            }
        }
        __syncthreads();

        float accA[4][4];
#pragma unroll
        for (int nt = 0; nt < 4; nt++)
#pragma unroll
            for (int q = 0; q < 4; q++) accA[nt][q] = 0.f;
#pragma unroll
        for (int ks = 0; ks < 8; ks++) {
            const int k0 = ks * 16 + 2 * c;
            const int ar = wm * 16 + g;
            uint32_t ah0 = *(const uint32_t*)&sm[SM_A_HI + ar * 136 + k0];
            uint32_t ah1 = *(const uint32_t*)&sm[SM_A_HI + (ar + 8) * 136 + k0];
            uint32_t ah2 = *(const uint32_t*)&sm[SM_A_HI + ar * 136 + k0 + 8];
            uint32_t ah3 = *(const uint32_t*)&sm[SM_A_HI + (ar + 8) * 136 + k0 + 8];
            uint32_t al0 = *(const uint32_t*)&sm[SM_A_LO + ar * 136 + k0];
            uint32_t al1 = *(const uint32_t*)&sm[SM_A_LO + (ar + 8) * 136 + k0];
            uint32_t al2 = *(const uint32_t*)&sm[SM_A_LO + ar * 136 + k0 + 8];
            uint32_t al3 = *(const uint32_t*)&sm[SM_A_LO + (ar + 8) * 136 + k0 + 8];
#pragma unroll
            for (int nt = 0; nt < 4; nt++) {
                const int br = wn * 32 + nt * 8 + g;
                uint32_t bh0 = *(const uint32_t*)&sm[SM_W_HI + br * 136 + k0];
                uint32_t bh1 = *(const uint32_t*)&sm[SM_W_HI + br * 136 + k0 + 8];
                uint32_t bl0 = *(const uint32_t*)&sm[SM_W_LO + br * 136 + k0];
                uint32_t bl1 = *(const uint32_t*)&sm[SM_W_LO + br * 136 + k0 + 8];
                MMA16816(accA[nt], ah0, ah1, ah2, ah3, bh0, bh1);
                MMA16816(accA[nt], ah0, ah1, ah2, ah3, bl0, bl1);
                MMA16816(accA[nt], al0, al1, al2, al3, bh0, bh1);
            }
        }
        {
            const int m0 = wm * 16 + g, m1 = m0 + 8;
#pragma unroll
            for (int nt = 0; nt < 4; nt++) {
                int nl = wn * 32 + nt * 8 + 2 * c;
                float2 bb = *(const float2*)&b1[chunk * 64 + nl];
                float v0 = fmaxf(accA[nt][0] + bb.x, 0.f);
                float v1 = fmaxf(accA[nt][1] + bb.y, 0.f);
                float v2 = fmaxf(accA[nt][2] + bb.x, 0.f);
                float v3 = fmaxf(accA[nt][3] + bb.y, 0.f);
                __nv_bfloat16 h0, l0, h1, l1;
                split_bf(v0, h0, l0); split_bf(v1, h1, l1);
                *(uint32_t*)&sm[SM_H_HI + m0 * 72 + nl] = pack2(h0, h1);
                *(uint32_t*)&sm[SM_H_LO + m0 * 72 + nl] = pack2(l0, l1);
                split_bf(v2, h0, l0); split_bf(v3, h1, l1);
                *(uint32_t*)&sm[SM_H_HI + m1 * 72 + nl] = pack2(h0, h1);
                *(uint32_t*)&sm[SM_H_LO + m1 * 72 + nl] = pack2(l0, l1);
            }
        }
        __syncthreads();

#pragma unroll
        for (int ks = 0; ks < 4; ks++) {
            const int k0 = ks * 16 + 2 * c;
            const int ar = wm * 16 + g;
            uint32_t ah0 = *(const uint32_t*)&sm[SM_H_HI + ar * 72 + k0];
            uint32_t ah1 = *(const uint32_t*)&sm[SM_H_HI + (ar + 8) * 72 + k0];
            uint32_t ah2 = *(const uint32_t*)&sm[SM_H_HI + ar * 72 + k0 + 8];
            uint32_t ah3 = *(const uint32_t*)&sm[SM_H_HI + (ar + 8) * 72 + k0 + 8];
            uint32_t al0 = *(const uint32_t*)&sm[SM_H_LO + ar * 72 + k0];
            uint32_t al1 = *(const uint32_t*)&sm[SM_H_LO + (ar + 8) * 72 + k0];
            uint32_t al2 = *(const uint32_t*)&sm[SM_H_LO + ar * 72 + k0 + 8];
            uint32_t al3 = *(const uint32_t*)&sm[SM_H_LO + (ar + 8) * 72 + k0 + 8];
#pragma unroll
            for (int nt = 0; nt < 4; nt++) {
                const int br = wn * 32 + nt * 8 + g;
                uint32_t bh0 = *(const uint32_t*)&sm[SM_W2_HI + br * 72 + k0];
                uint32_t bh1 = *(const uint32_t*)&sm[SM_W2_HI + br * 72 + k0 + 8];
                uint32_t bl0 = *(const uint32_t*)&sm[SM_W2_LO + br * 72 + k0];
                uint32_t bl1 = *(const uint32_t*)&sm[SM_W2_LO + br * 72 + k0 + 8];
                MMA16816(acc2[nt], ah0, ah1, ah2, ah3, bh0, bh1);
                MMA16816(acc2[nt], ah0, ah1, ah2, ah3, bl0, bl1);
                MMA16816(acc2[nt], al0, al1, al2, al3, bh0, bh1);
            }
        }
    }

    const int m0 = m_block + wm * 16 + g;
    const int m1 = m0 + 8;
    float dv0 = (m0 < N_NODES) ? g_dinv[m0] : 0.f;
    float dv1 = (m1 < N_NODES) ? g_dinv[m1] : 0.f;
#pragma unroll
    for (int nt = 0; nt < 4; nt++) {
        int n = wn * 32 + nt * 8 + 2 * c;
        if (m0 < N_NODES)
            *(float2*)&g_zs[(size_t)m0 * F_OUT + n] =
                make_float2(acc2[nt][0] * dv0, acc2[nt][1] * dv0);
        if (m1 < N_NODES)
            *(float2*)&g_zs[(size_t)m1 * F_OUT + n] =
                make_float2(acc2[nt][2] * dv1, acc2[nt][3] * dv1);
    }
}

// ------- agg2 + epilogue: 2 nodes per warp, float4 lanes, streaming out ---
__global__ void k_agg2out(const float* __restrict__ b2, float* __restrict__ out,
                          int copies) {
    int gw = (blockIdx.x * blockDim.x + threadIdx.x) >> 5;
    int lane = threadIdx.x & 31;
    int node = gw * 2 + (lane >> 4);        // half-warp per node
    int l16 = lane & 15;
    if (node >= N_NODES) return;
    size_t loff = (size_t)l16 * 4;
    float4 acc = *(const float4*)&g_zs[(size_t)node * F_OUT + loff];
    const int* bc = &g_bcol[(size_t)node * BUCKET];
    int cnt = g_cnt[node];
    if (cnt > BUCKET) cnt = BUCKET;
    int i = 0;
    for (; i + 4 <= cnt; i += 4) {
        int c0 = bc[i];
        int c1 = bc[i + 1];
        int c2 = bc[i + 2];
        int c3 = bc[i + 3];
        float4 v0 = *(const float4*)&g_zs[(size_t)c0 * F_OUT + loff];
        float4 v1 = *(const float4*)&g_zs[(size_t)c1 * F_OUT + loff];
        float4 v2 = *(const float4*)&g_zs[(size_t)c2 * F_OUT + loff];
        float4 v3 = *(const float4*)&g_zs[(size_t)c3 * F_OUT + loff];
        acc.x += v0.x + v1.x + v2.x + v3.x;
        acc.y += v0.y + v1.y + v2.y + v3.y;
        acc.z += v0.z + v1.z + v2.z + v3.z;
        acc.w += v0.w + v1.w + v2.w + v3.w;
    }
    for (; i < cnt; i++) {
        int c = bc[i];
        float4 v = *(const float4*)&g_zs[(size_t)c * F_OUT + loff];
        acc.x += v.x; acc.y += v.y; acc.z += v.z; acc.w += v.w;
    }
    float dv = g_dinv[node];
    float4 bb = *(const float4*)&b2[loff];
    float4 vv;
    vv.x = dv * acc.x + bb.x;
    vv.y = dv * acc.y + bb.y;
    vv.z = dv * acc.z + bb.z;
    vv.w = dv * acc.w + bb.w;
    float m = fmaxf(fmaxf(vv.x, vv.y), fmaxf(vv.z, vv.w));
#pragma unroll
    for (int o = 8; o > 0; o >>= 1)
        m = fmaxf(m, __shfl_xor_sync(0xFFFFFFFFu, m, o));
    float sum = expf(vv.x - m) + expf(vv.y - m) + expf(vv.z - m) + expf(vv.w - m);
#pragma unroll
    for (int o = 8; o > 0; o >>= 1)
        sum += __shfl_xor_sync(0xFFFFFFFFu, sum, o);
    float lse = m + logf(sum);
    float4 r = make_float4(vv.x - lse, vv.y - lse, vv.z - lse, vv.w - lse);
    size_t base = (size_t)node * F_OUT + loff;
    size_t stride = (size_t)N_NODES * F_OUT;
#pragma unroll 4
    for (int cpy = 0; cpy < copies; cpy++)
        __stcs((float4*)&out[(size_t)cpy * stride + base], r);
}

// ---------------- launch ----------------
extern "C" void kernel_launch(void* const* d_in, const int* in_sizes, int n_in,
                              void* d_out, int out_size) {
    const float* x  = (const float*)d_in[0];
    const float* W1 = (const float*)d_in[1];
    const float* b1 = (const float*)d_in[2];
    const float* W2 = (const float*)d_in[3];
    const float* b2 = (const float*)d_in[4];
    const void* edge = d_in[5];
    const int E = in_sizes[5] / 2;
    float* out = (float*)d_out;
    const int copies = out_size / (N_NODES * F_OUT);   // batch * pred_steps = 24

    static int smem_set = 0;
    if (!smem_set) {
        cudaFuncSetAttribute(k_mlp, cudaFuncAttributeMaxDynamicSharedMemorySize,
                             SM_TOTAL_ELEMS * 2);
        smem_set = 1;
    }

    k_pre<<<512, 256>>>((const int*)edge, (long long)E * 2);
    {
        int fillBlocks = (E + 255) / 256;
        k_fill_w<<<fillBlocks + WCONV_BLOCKS, 256>>>(edge, E, W1, W2, fillBlocks);
    }
    k_dinv<<<(N_NODES + 255) / 256, 256>>>();
    k_mlp<<<(N_NODES + 63) / 64, 256, SM_TOTAL_ELEMS * 2>>>(x, b1);
    k_agg2out<<<((N_NODES + 1) / 2 * 32 + 255) / 256, 256>>>(b2, out, copies);
}

// round 10
// speedup vs baseline: 1.1406x; 1.1406x over previous
#include <cuda_runtime.h>
#include <cuda_bf16.h>
#include <cstdint>
#include <cstddef>
#include <math.h>

#define N_NODES 50000
#define F_IN    128
#define F_HID   256
#define F_OUT   64
#define BUCKET  192
#define WCONV_THREADS (F_IN * F_HID + F_HID * F_OUT)
#define WCONV_BLOCKS  ((WCONV_THREADS + 255) / 256)

// ---------------- static scratch (no allocation allowed) ----------------
__device__ int   g_any_odd = 0;   // edge dtype probe: 1 => int32, 0 => int64
__device__ int   g_cnt [N_NODES];               // neighbor count (excl self)
__device__ __align__(16) float g_dinv[N_NODES];
__device__ int   g_bcol[(size_t)N_NODES * BUCKET];   // bucketed adjacency
__device__ __align__(16) __nv_bfloat16 g_a1hi[(size_t)N_NODES * F_IN];
__device__ __align__(16) __nv_bfloat16 g_a1lo[(size_t)N_NODES * F_IN];
__device__ __align__(16) __nv_bfloat16 g_w1t_hi[F_HID * F_IN];  // [256][128]
__device__ __align__(16) __nv_bfloat16 g_w1t_lo[F_HID * F_IN];
__device__ __align__(16) __nv_bfloat16 g_w2t_hi[F_OUT * F_HID]; // [64][256]
__device__ __align__(16) __nv_bfloat16 g_w2t_lo[F_OUT * F_HID];
__device__ __align__(16) float g_zs [(size_t)N_NODES * F_OUT];  // (h1@W2)*dinv

__device__ __forceinline__ int edge_at(const void* e, long long i, int is32) {
    if (is32) return ((const int*)e)[i];
    return (int)((const long long*)e)[i];
}

__device__ __forceinline__ void split_bf(float v, __nv_bfloat16& h, __nv_bfloat16& l) {
    h = __float2bfloat16(v);
    l = __float2bfloat16(v - __bfloat162float(h));
}
__device__ __forceinline__ uint32_t pack2(__nv_bfloat16 a, __nv_bfloat16 b) {
    return (uint32_t)__bfloat16_as_ushort(a) | ((uint32_t)__bfloat16_as_ushort(b) << 16);
}

#define MMA16816(d, a0,a1,a2,a3, b0,b1) \
  asm volatile("mma.sync.aligned.m16n8k16.row.col.f32.bf16.bf16.f32 " \
    "{%0,%1,%2,%3}, {%4,%5,%6,%7}, {%8,%9}, {%0,%1,%2,%3};" \
    : "+f"(d[0]), "+f"(d[1]), "+f"(d[2]), "+f"(d[3]) \
    : "r"(a0), "r"(a1), "r"(a2), "r"(a3), "r"(b0), "r"(b1))

// ---------------- pre: zero counts + dtype probe --------------
__global__ void k_pre(const int* __restrict__ ew, long long nwords) {
    long long i = (long long)blockIdx.x * blockDim.x + threadIdx.x;
    long long stride = (long long)gridDim.x * blockDim.x;
    for (long long q = i; q < N_NODES; q += stride)
        g_cnt[q] = 0;
    int any = 0;
    for (long long t = i * 2 + 1; t < nwords; t += 2 * stride)
        any |= ew[t];
    if (any) g_any_odd = 1;
}

// ------- bucket adjacency fill; spare blocks do weight split -----------
__global__ void k_fill_w(const void* __restrict__ edge, int E,
                         const float* __restrict__ W1, const float* __restrict__ W2,
                         int fillBlocks) {
    if (blockIdx.x < fillBlocks) {
        int is32 = g_any_odd;
        int i = blockIdx.x * blockDim.x + threadIdx.x;
        int stride = fillBlocks * blockDim.x;
        for (int e = i; e < E; e += stride) {
            int r = edge_at(edge, e, is32);
            int c = edge_at(edge, (long long)e + E, is32);
            int pos = atomicAdd(&g_cnt[r], 1);
            if (pos < BUCKET)
                g_bcol[(size_t)r * BUCKET + pos] = c;
        }
    } else {
        int i = (blockIdx.x - fillBlocks) * blockDim.x + threadIdx.x;
        if (i < F_IN * F_HID) {
            int k = i / F_HID, n = i % F_HID;
            __nv_bfloat16 h, l;
            split_bf(W1[i], h, l);
            g_w1t_hi[n * F_IN + k] = h;
            g_w1t_lo[n * F_IN + k] = l;
        }
        int j = i - F_IN * F_HID;
        if (j >= 0 && j < F_HID * F_OUT) {
            int k = j / F_OUT, n = j % F_OUT;
            __nv_bfloat16 h, l;
            split_bf(W2[j], h, l);
            g_w2t_hi[n * F_HID + k] = h;
            g_w2t_lo[n * F_HID + k] = l;
        }
    }
}

// ---------------- dinv = rsqrt(cnt + 1) ----------------
__global__ void k_dinv() {
    int i = blockIdx.x * blockDim.x + threadIdx.x;
    if (i < N_NODES)
        g_dinv[i] = rsqrtf((float)(g_cnt[i] + 1));
}

// ------- agg1: a1 = dinv[r]*(dinv[r]x[r] + Σ dinv[c]x[c]);  bf16 hi/lo ----
__global__ void k_agg1(const float* __restrict__ x) {
    int gw = (blockIdx.x * blockDim.x + threadIdx.x) >> 5;
    int lane = threadIdx.x & 31;
    if (gw >= N_NODES) return;
    size_t loff = (size_t)lane * 4;
    float dvr = g_dinv[gw];
    float4 acc = *(const float4*)&x[(size_t)gw * F_IN + loff];
    acc.x *= dvr; acc.y *= dvr; acc.z *= dvr; acc.w *= dvr;
    const int* bc = &g_bcol[(size_t)gw * BUCKET];
    int cnt = g_cnt[gw];
    if (cnt > BUCKET) cnt = BUCKET;
    int i = 0;
    for (; i + 8 <= cnt; i += 8) {
        int c0 = bc[i];
        int c1 = bc[i + 1];
        int c2 = bc[i + 2];
        int c3 = bc[i + 3];
        int c4 = bc[i + 4];
        int c5 = bc[i + 5];
        int c6 = bc[i + 6];
        int c7 = bc[i + 7];
        float d0 = g_dinv[c0], d1 = g_dinv[c1], d2 = g_dinv[c2], d3 = g_dinv[c3];
        float d4 = g_dinv[c4], d5 = g_dinv[c5], d6 = g_dinv[c6], d7 = g_dinv[c7];
        float4 v0 = *(const float4*)&x[(size_t)c0 * F_IN + loff];
        float4 v1 = *(const float4*)&x[(size_t)c1 * F_IN + loff];
        float4 v2 = *(const float4*)&x[(size_t)c2 * F_IN + loff];
        float4 v3 = *(const float4*)&x[(size_t)c3 * F_IN + loff];
        float4 v4 = *(const float4*)&x[(size_t)c4 * F_IN + loff];
        float4 v5 = *(const float4*)&x[(size_t)c5 * F_IN + loff];
        float4 v6 = *(const float4*)&x[(size_t)c6 * F_IN + loff];
        float4 v7 = *(const float4*)&x[(size_t)c7 * F_IN + loff];
        acc.x += d0 * v0.x + d1 * v1.x + d2 * v2.x + d3 * v3.x
               + d4 * v4.x + d5 * v5.x + d6 * v6.x + d7 * v7.x;
        acc.y += d0 * v0.y + d1 * v1.y + d2 * v2.y + d3 * v3.y
               + d4 * v4.y + d5 * v5.y + d6 * v6.y + d7 * v7.y;
        acc.z += d0 * v0.z + d1 * v1.z + d2 * v2.z + d3 * v3.z
               + d4 * v4.z + d5 * v5.z + d6 * v6.z + d7 * v7.z;
        acc.w += d0 * v0.w + d1 * v1.w + d2 * v2.w + d3 * v3.w
               + d4 * v4.w + d5 * v5.w + d6 * v6.w + d7 * v7.w;
    }
    for (; i < cnt; i++) {
        int c = bc[i];
        float dc = g_dinv[c];
        float4 v = *(const float4*)&x[(size_t)c * F_IN + loff];
        acc.x += dc * v.x; acc.y += dc * v.y;
        acc.z += dc * v.z; acc.w += dc * v.w;
    }
    acc.x *= dvr; acc.y *= dvr; acc.z *= dvr; acc.w *= dvr;
    __nv_bfloat16 h0, l0, h1, l1, h2, l2, h3, l3;
    split_bf(acc.x, h0, l0); split_bf(acc.y, h1, l1);
    split_bf(acc.z, h2, l2); split_bf(acc.w, h3, l3);
    uint2 hv = make_uint2(pack2(h0, h1), pack2(h2, h3));
    uint2 lv = make_uint2(pack2(l0, l1), pack2(l2, l3));
    *(uint2*)&g_a1hi[(size_t)gw * F_IN + loff] = hv;
    *(uint2*)&g_a1lo[(size_t)gw * F_IN + loff] = lv;
}

// ---------------- fused MLP: zs = relu(a1@W1+b1)@W2 * dinv ----------------
#define SM_A_HI 0
#define SM_A_LO 8704
#define SM_W_HI 17408
#define SM_W_LO 26112
#define SM_H_HI 34816
#define SM_H_LO 39424
#define SM_W2_HI 44032
#define SM_W2_LO 48640
#define SM_TOTAL_ELEMS 53248   // * 2 bytes = 106496

__global__ __launch_bounds__(256, 2) void k_mlp(const float* __restrict__ b1) {
    extern __shared__ __nv_bfloat16 sm[];
    const int tid = threadIdx.x;
    const int lane = tid & 31, warp = tid >> 5;
    const int wm = warp & 3, wn = warp >> 2;
    const int g = lane >> 2, c = lane & 3;
    const int m_block = blockIdx.x * 64;

    // load A tile (64 x 128, hi/lo)
    {
        int row = tid >> 4;
        int col = (tid & 15) * 8;
#pragma unroll
        for (int r = 0; r < 4; r++) {
            int rr = row + r * 16;
            int m = m_block + rr;
            uint4 vh = make_uint4(0u, 0u, 0u, 0u), vl = vh;
            if (m < N_NODES) {
                size_t go = (size_t)m * F_IN + col;
                vh = *(const uint4*)(g_a1hi + go);
                vl = *(const uint4*)(g_a1lo + go);
            }
            *(uint4*)&sm[SM_A_HI + rr * 136 + col] = vh;
            *(uint4*)&sm[SM_A_LO + rr * 136 + col] = vl;
        }
    }

    float acc2[4][4];
#pragma unroll
    for (int nt = 0; nt < 4; nt++)
#pragma unroll
        for (int q = 0; q < 4; q++) acc2[nt][q] = 0.f;

#pragma unroll
    for (int chunk = 0; chunk < 4; chunk++) {
        __syncthreads();
        {
            int row = tid >> 4;
            int col = (tid & 15) * 8;
#pragma unroll
            for (int r = 0; r < 4; r++) {
                int rr = row + r * 16;
                size_t go = (size_t)(chunk * 64 + rr) * F_IN + col;
                *(uint4*)&sm[SM_W_HI + rr * 136 + col] = *(const uint4*)(g_w1t_hi + go);
                *(uint4*)&sm[SM_W_LO + rr * 136 + col] = *(const uint4*)(g_w1t_lo + go);
            }
            int row2 = tid >> 3;
            int col2 = (tid & 7) * 8;
#pragma unroll
            for (int r = 0; r < 2; r++) {
                int rr = row2 + r * 32;
                size_t go = (size_t)rr * F_HID + chunk * 64 + col2;
                *(uint4*)&sm[SM_W2_HI + rr * 72 + col2] = *(const uint4*)(g_w2t_hi + go);
                *(uint4*)&sm[SM_W2_LO + rr * 72 + col2] = *(const uint4*)(g_w2t_lo + go);
            }
        }
        __syncthreads();

        float accA[4][4];
#pragma unroll
        for (int nt = 0; nt < 4; nt++)
#pragma unroll
            for (int q = 0; q < 4; q++) accA[nt][q] = 0.f;
#pragma unroll
        for (int ks = 0; ks < 8; ks++) {
            const int k0 = ks * 16 + 2 * c;
            const int ar = wm * 16 + g;
            uint32_t ah0 = *(const uint32_t*)&sm[SM_A_HI + ar * 136 + k0];
            uint32_t ah1 = *(const uint32_t*)&sm[SM_A_HI + (ar + 8) * 136 + k0];
            uint32_t ah2 = *(const uint32_t*)&sm[SM_A_HI + ar * 136 + k0 + 8];
            uint32_t ah3 = *(const uint32_t*)&sm[SM_A_HI + (ar + 8) * 136 + k0 + 8];
            uint32_t al0 = *(const uint32_t*)&sm[SM_A_LO + ar * 136 + k0];
            uint32_t al1 = *(const uint32_t*)&sm[SM_A_LO + (ar + 8) * 136 + k0];
            uint32_t al2 = *(const uint32_t*)&sm[SM_A_LO + ar * 136 + k0 + 8];
            uint32_t al3 = *(const uint32_t*)&sm[SM_A_LO + (ar + 8) * 136 + k0 + 8];
#pragma unroll
            for (int nt = 0; nt < 4; nt++) {
                const int br = wn * 32 + nt * 8 + g;
                uint32_t bh0 = *(const uint32_t*)&sm[SM_W_HI + br * 136 + k0];
                uint32_t bh1 = *(const uint32_t*)&sm[SM_W_HI + br * 136 + k0 + 8];
                uint32_t bl0 = *(const uint32_t*)&sm[SM_W_LO + br * 136 + k0];
                uint32_t bl1 = *(const uint32_t*)&sm[SM_W_LO + br * 136 + k0 + 8];
                MMA16816(accA[nt], ah0, ah1, ah2, ah3, bh0, bh1);
                MMA16816(accA[nt], ah0, ah1, ah2, ah3, bl0, bl1);
                MMA16816(accA[nt], al0, al1, al2, al3, bh0, bh1);
            }
        }
        {
            const int m0 = wm * 16 + g, m1 = m0 + 8;
#pragma unroll
            for (int nt = 0; nt < 4; nt++) {
                int nl = wn * 32 + nt * 8 + 2 * c;
                float2 bb = *(const float2*)&b1[chunk * 64 + nl];
                float v0 = fmaxf(accA[nt][0] + bb.x, 0.f);
                float v1 = fmaxf(accA[nt][1] + bb.y, 0.f);
                float v2 = fmaxf(accA[nt][2] + bb.x, 0.f);
                float v3 = fmaxf(accA[nt][3] + bb.y, 0.f);
                __nv_bfloat16 h0, l0, h1, l1;
                split_bf(v0, h0, l0); split_bf(v1, h1, l1);
                *(uint32_t*)&sm[SM_H_HI + m0 * 72 + nl] = pack2(h0, h1);
                *(uint32_t*)&sm[SM_H_LO + m0 * 72 + nl] = pack2(l0, l1);
                split_bf(v2, h0, l0); split_bf(v3, h1, l1);
                *(uint32_t*)&sm[SM_H_HI + m1 * 72 + nl] = pack2(h0, h1);
                *(uint32_t*)&sm[SM_H_LO + m1 * 72 + nl] = pack2(l0, l1);
            }
        }
        __syncthreads();

#pragma unroll
        for (int ks = 0; ks < 4; ks++) {
            const int k0 = ks * 16 + 2 * c;
            const int ar = wm * 16 + g;
            uint32_t ah0 = *(const uint32_t*)&sm[SM_H_HI + ar * 72 + k0];
            uint32_t ah1 = *(const uint32_t*)&sm[SM_H_HI + (ar + 8) * 72 + k0];
            uint32_t ah2 = *(const uint32_t*)&sm[SM_H_HI + ar * 72 + k0 + 8];
            uint32_t ah3 = *(const uint32_t*)&sm[SM_H_HI + (ar + 8) * 72 + k0 + 8];
            uint32_t al0 = *(const uint32_t*)&sm[SM_H_LO + ar * 72 + k0];
            uint32_t al1 = *(const uint32_t*)&sm[SM_H_LO + (ar + 8) * 72 + k0];
            uint32_t al2 = *(const uint32_t*)&sm[SM_H_LO + ar * 72 + k0 + 8];
            uint32_t al3 = *(const uint32_t*)&sm[SM_H_LO + (ar + 8) * 72 + k0 + 8];
#pragma unroll
            for (int nt = 0; nt < 4; nt++) {
                const int br = wn * 32 + nt * 8 + g;
                uint32_t bh0 = *(const uint32_t*)&sm[SM_W2_HI + br * 72 + k0];
                uint32_t bh1 = *(const uint32_t*)&sm[SM_W2_HI + br * 72 + k0 + 8];
                uint32_t bl0 = *(const uint32_t*)&sm[SM_W2_LO + br * 72 + k0];
                uint32_t bl1 = *(const uint32_t*)&sm[SM_W2_LO + br * 72 + k0 + 8];
                MMA16816(acc2[nt], ah0, ah1, ah2, ah3, bh0, bh1);
                MMA16816(acc2[nt], ah0, ah1, ah2, ah3, bl0, bl1);
                MMA16816(acc2[nt], al0, al1, al2, al3, bh0, bh1);
            }
        }
    }

    const int m0 = m_block + wm * 16 + g;
    const int m1 = m0 + 8;
    float dv0 = (m0 < N_NODES) ? g_dinv[m0] : 0.f;
    float dv1 = (m1 < N_NODES) ? g_dinv[m1] : 0.f;
#pragma unroll
    for (int nt = 0; nt < 4; nt++) {
        int n = wn * 32 + nt * 8 + 2 * c;
        if (m0 < N_NODES)
            *(float2*)&g_zs[(size_t)m0 * F_OUT + n] =
                make_float2(acc2[nt][0] * dv0, acc2[nt][1] * dv0);
        if (m1 < N_NODES)
            *(float2*)&g_zs[(size_t)m1 * F_OUT + n] =
                make_float2(acc2[nt][2] * dv1, acc2[nt][3] * dv1);
    }
}

// ------- agg2 + epilogue: 2 nodes per warp, float4 lanes, streaming out ---
__global__ void k_agg2out(const float* __restrict__ b2, float* __restrict__ out,
                          int copies) {
    int gw = (blockIdx.x * blockDim.x + threadIdx.x) >> 5;
    int lane = threadIdx.x & 31;
    int node = gw * 2 + (lane >> 4);        // half-warp per node
    int l16 = lane & 15;
    if (node >= N_NODES) return;
    size_t loff = (size_t)l16 * 4;
    float4 acc = *(const float4*)&g_zs[(size_t)node * F_OUT + loff];
    const int* bc = &g_bcol[(size_t)node * BUCKET];
    int cnt = g_cnt[node];
    if (cnt > BUCKET) cnt = BUCKET;
    int i = 0;
    for (; i + 4 <= cnt; i += 4) {
        int c0 = bc[i];
        int c1 = bc[i + 1];
        int c2 = bc[i + 2];
        int c3 = bc[i + 3];
        float4 v0 = *(const float4*)&g_zs[(size_t)c0 * F_OUT + loff];
        float4 v1 = *(const float4*)&g_zs[(size_t)c1 * F_OUT + loff];
        float4 v2 = *(const float4*)&g_zs[(size_t)c2 * F_OUT + loff];
        float4 v3 = *(const float4*)&g_zs[(size_t)c3 * F_OUT + loff];
        acc.x += v0.x + v1.x + v2.x + v3.x;
        acc.y += v0.y + v1.y + v2.y + v3.y;
        acc.z += v0.z + v1.z + v2.z + v3.z;
        acc.w += v0.w + v1.w + v2.w + v3.w;
    }
    for (; i < cnt; i++) {
        int c = bc[i];
        float4 v = *(const float4*)&g_zs[(size_t)c * F_OUT + loff];
        acc.x += v.x; acc.y += v.y; acc.z += v.z; acc.w += v.w;
    }
    float dv = g_dinv[node];
    float4 bb = *(const float4*)&b2[loff];
    float4 vv;
    vv.x = dv * acc.x + bb.x;
    vv.y = dv * acc.y + bb.y;
    vv.z = dv * acc.z + bb.z;
    vv.w = dv * acc.w + bb.w;
    float m = fmaxf(fmaxf(vv.x, vv.y), fmaxf(vv.z, vv.w));
#pragma unroll
    for (int o = 8; o > 0; o >>= 1)
        m = fmaxf(m, __shfl_xor_sync(0xFFFFFFFFu, m, o));
    float sum = expf(vv.x - m) + expf(vv.y - m) + expf(vv.z - m) + expf(vv.w - m);
#pragma unroll
    for (int o = 8; o > 0; o >>= 1)
        sum += __shfl_xor_sync(0xFFFFFFFFu, sum, o);
    float lse = m + logf(sum);
    float4 r = make_float4(vv.x - lse, vv.y - lse, vv.z - lse, vv.w - lse);
    size_t base = (size_t)node * F_OUT + loff;
    size_t stride = (size_t)N_NODES * F_OUT;
#pragma unroll 4
    for (int cpy = 0; cpy < copies; cpy++)
        __stcs((float4*)&out[(size_t)cpy * stride + base], r);
}

// ---------------- launch ----------------
extern "C" void kernel_launch(void* const* d_in, const int* in_sizes, int n_in,
                              void* d_out, int out_size) {
    const float* x  = (const float*)d_in[0];
    const float* W1 = (const float*)d_in[1];
    const float* b1 = (const float*)d_in[2];
    const float* W2 = (const float*)d_in[3];
    const float* b2 = (const float*)d_in[4];
    const void* edge = d_in[5];
    const int E = in_sizes[5] / 2;
    float* out = (float*)d_out;
    const int copies = out_size / (N_NODES * F_OUT);   // batch * pred_steps = 24

    static int smem_set = 0;
    if (!smem_set) {
        cudaFuncSetAttribute(k_mlp, cudaFuncAttributeMaxDynamicSharedMemorySize,
                             SM_TOTAL_ELEMS * 2);
        smem_set = 1;
    }

    k_pre<<<512, 256>>>((const int*)edge, (long long)E * 2);
    {
        int fillBlocks = (E + 255) / 256;
        k_fill_w<<<fillBlocks + WCONV_BLOCKS, 256>>>(edge, E, W1, W2, fillBlocks);
    }
    k_dinv<<<(N_NODES + 255) / 256, 256>>>();
    k_agg1<<<(N_NODES * 32 + 255) / 256, 256>>>(x);
    k_mlp<<<(N_NODES + 63) / 64, 256, SM_TOTAL_ELEMS * 2>>>(b1);
    k_agg2out<<<((N_NODES + 1) / 2 * 32 + 255) / 256, 256>>>(b2, out, copies);
}